// round 2
// baseline (speedup 1.0000x reference)
#include <cuda_runtime.h>
#include <cuda_bf16.h>
#include <mma.h>
#include <cstdint>
#include <cstddef>

using namespace nvcuda;
typedef __nv_bfloat16 bf16;

// ---------------- problem constants ----------------
// B=2, N=4096, dim=512, C=256, Hn=8, hd=32, Hs=64, 3C=768, PW_GROUPS=24
#define ATT_SCALE 0.17677669529663687f   // 32^-0.5

// ---------------- scratch (device globals; no allocation allowed) ----------
// NOTE: __align__(256) is load-bearing: these are accessed via uint4/uint2.
__device__ __align__(256) bf16 g_xb [8192u*512u];     // x in bf16            8 MB
__device__ __align__(256) bf16 g_W1 [512u*768u];      // w_reduce @ w_qkv
__device__ __align__(256) bf16 g_W2 [3072u*768u];     // folded reduce2 (pw absorbed)
__device__ __align__(256) bf16 g_wp [256u*512u];      // w_proj bf16
__device__ __align__(256) bf16 g_cat[25165824u];      // [2][3072][4096]      48 MB
__device__ __align__(256) bf16 g_msq[6291456u];       // [2][4096][768]       12 MB
__device__ __align__(256) bf16 g_ao [8192u*256u];     // attention out         4 MB

// ---------------- elementwise fp32 -> bf16 converts ------------------------
template<int W>
__global__ void k_convert(const float* __restrict__ src) {
    bf16* dst = (W == 0) ? g_xb : (W == 1) ? g_W2 : g_wp;
    int i = (blockIdx.x * 256 + threadIdx.x) * 4;
    float4 v = *(const float4*)(src + i);
    uint2 pack;
    bf16* t = (bf16*)&pack;
    t[0] = __float2bfloat16(v.x); t[1] = __float2bfloat16(v.y);
    t[2] = __float2bfloat16(v.z); t[3] = __float2bfloat16(v.w);
    *(uint2*)(dst + i) = pack;
}

// ---------------- fold W1 = w_reduce @ w_qkv  ([512,256]x[256,768]) --------
__global__ void k_fold_w1(const float* __restrict__ wr, const float* __restrict__ wq) {
    __shared__ float rows[8 * 256];
    int d0 = blockIdx.x * 8;
    for (int i = threadIdx.x; i < 2048; i += 256) rows[i] = wr[d0 * 256 + i];
    __syncthreads();
    for (int j = threadIdx.x; j < 768; j += 256) {
        float s[8] = {0,0,0,0,0,0,0,0};
        for (int c = 0; c < 256; c++) {
            float qv = wq[c * 768 + j];
            #pragma unroll
            for (int r = 0; r < 8; r++) s[r] += rows[r * 256 + c] * qv;
        }
        #pragma unroll
        for (int r = 0; r < 8; r++) g_W1[(d0 + r) * 768 + j] = __float2bfloat16(s[r]);
    }
}

// ---------------- fold pw_b into w_reduce2 block b --------------------------
// W2f[768 + b*768 + g*32 + il, j] = sum_o pw_b[(g*32+o)*32 + il] * wr2[(b+1)*768 + g*32 + o, j]
__global__ void k_fold_w2(const float* __restrict__ pw0, const float* __restrict__ pw1,
                          const float* __restrict__ pw2, const float* __restrict__ wr2) {
    __shared__ float coef[1024];               // [o][il] 32x32 slab
    int g = blockIdx.x;                        // 0..23
    int bidx = blockIdx.y;                     // 0..2
    const float* pw = (bidx == 0) ? pw0 : (bidx == 1) ? pw1 : pw2;
    for (int f = threadIdx.x; f < 1024; f += 256) coef[f] = pw[g * 1024 + f];
    __syncthreads();
    for (int j = threadIdx.x; j < 768; j += 256) {
        float wv[32];
        #pragma unroll
        for (int o = 0; o < 32; o++)
            wv[o] = wr2[((size_t)(bidx + 1) * 768 + g * 32 + o) * 768 + j];
        for (int il = 0; il < 32; il++) {
            float s = 0.f;
            #pragma unroll
            for (int o = 0; o < 32; o++) s += coef[o * 32 + il] * wv[o];
            g_W2[((size_t)768 + bidx * 768 + g * 32 + il) * 768 + j] = __float2bfloat16(s);
        }
    }
}

// ---------------- depthwise convs (3x3, 5x5, 7x7) in one pass ---------------
__global__ void k_conv(const float* __restrict__ dw0, const float* __restrict__ dw1,
                       const float* __restrict__ dw2) {
    __shared__ bf16 t[70][72];
    __shared__ float w3[9], w5[25], w7[49];
    int ch = blockIdx.x, b = blockIdx.y, tid = threadIdx.x;
    if (tid < 9)  w3[tid] = dw0[ch * 9  + tid];
    if (tid < 25) w5[tid] = dw1[ch * 25 + tid];
    if (tid < 49) w7[tid] = dw2[ch * 49 + tid];
    const bf16* in = g_cat + ((size_t)b * 3072 + ch) * 4096;
    for (int u = tid; u < 70 * 70; u += 256) {
        int ty = u / 70, tx = u % 70;
        int iy = ty - 3, ix = tx - 3;
        bf16 v = __float2bfloat16(0.f);
        if ((unsigned)iy < 64u && (unsigned)ix < 64u) v = in[iy * 64 + ix];
        t[ty][tx] = v;
    }
    __syncthreads();
    bf16* o3 = g_cat + ((size_t)b * 3072 +  768 + ch) * 4096;
    bf16* o5 = g_cat + ((size_t)b * 3072 + 1536 + ch) * 4096;
    bf16* o7 = g_cat + ((size_t)b * 3072 + 2304 + ch) * 4096;
    for (int it = 0; it < 16; it++) {
        int p = tid + it * 256;
        int y = p >> 6, x = p & 63;
        float a3 = 0.f, a5 = 0.f, a7 = 0.f;
        #pragma unroll
        for (int dy = 0; dy < 7; dy++)
            #pragma unroll
            for (int dx = 0; dx < 7; dx++) {
                float v = __bfloat162float(t[y + dy][x + dx]);
                a7 += v * w7[dy * 7 + dx];
                if (dy >= 1 && dy <= 5 && dx >= 1 && dx <= 5)
                    a5 += v * w5[(dy - 1) * 5 + (dx - 1)];
                if (dy >= 2 && dy <= 4 && dx >= 2 && dx <= 4)
                    a3 += v * w3[(dy - 2) * 3 + (dx - 2)];
            }
        o3[p] = __float2bfloat16(a3);
        o5[p] = __float2bfloat16(a5);
        o7[p] = __float2bfloat16(a7);
    }
}

// ---------------- generic bf16 WMMA GEMM, 128x64 tile, 8 warps --------------
// MODE 0: qkv = xb @ W1           -> transposed store into g_cat (channel-major)
// MODE 1: msq = cat^T @ W2f       -> row-major bf16 g_msq (A col-major, per batch)
// MODE 2: out = ao  @ wp  + bias  -> fp32 d_out
template<int MODE>
__global__ void k_gemm(float* __restrict__ OUT, const float* __restrict__ bias) {
    constexpr bool ACOL = (MODE == 1);
    constexpr int  K    = (MODE == 0) ? 512 : (MODE == 1) ? 3072 : 256;
    constexpr int  LDA  = (MODE == 0) ? 512 : (MODE == 1) ? 4096 : 256;
    constexpr int  LDB  = (MODE == 2) ? 512 : 768;

    extern __shared__ char sm[];
    bf16*  As  = (bf16*)sm;                // row: 128x48, col: 32x144
    bf16*  Bs  = (bf16*)(sm + 12288);      // 32x80
    float* Csm = (float*)sm;               // 128x72 (reused after k-loop)

    const int tid = threadIdx.x;
    const int warp = tid >> 5;
    const int wm = warp >> 1, wn = warp & 1;
    const int n0 = blockIdx.x * 64;
    const int m0 = blockIdx.y * 128;
    const int z  = blockIdx.z;

    const bf16* A; const bf16* Bm;
    if (MODE == 0)      { A = g_xb;                            Bm = g_W1; }
    else if (MODE == 1) { A = g_cat + (size_t)z * 3072 * 4096; Bm = g_W2; }
    else                { A = g_ao;                            Bm = g_wp; }

    wmma::fragment<wmma::accumulator, 16, 16, 16, float> acc[2][2];
    #pragma unroll
    for (int i = 0; i < 2; i++)
        #pragma unroll
        for (int j = 0; j < 2; j++) wmma::fill_fragment(acc[i][j], 0.f);

    for (int k0 = 0; k0 < K; k0 += 32) {
        if (ACOL) {
            #pragma unroll
            for (int it = 0; it < 2; it++) {
                int q = tid + it * 256;
                int k = q >> 4, mm = (q & 15) * 8;
                *(uint4*)(As + k * 144 + mm) =
                    *(const uint4*)(A + (size_t)(k0 + k) * LDA + m0 + mm);
            }
        } else {
            #pragma unroll
            for (int it = 0; it < 2; it++) {
                int q = tid + it * 256;
                int m = q >> 2, kk = (q & 3) * 8;
                *(uint4*)(As + m * 48 + kk) =
                    *(const uint4*)(A + (size_t)(m0 + m) * LDA + k0 + kk);
            }
        }
        {
            int k = tid >> 3, nn = (tid & 7) * 8;
            *(uint4*)(Bs + k * 80 + nn) =
                *(const uint4*)(Bm + (size_t)(k0 + k) * LDB + n0 + nn);
        }
        __syncthreads();
        #pragma unroll
        for (int kk = 0; kk < 32; kk += 16) {
            wmma::fragment<wmma::matrix_b, 16, 16, 16, bf16, wmma::row_major> bfv[2];
            wmma::load_matrix_sync(bfv[0], Bs + kk * 80 + wn * 32,      80);
            wmma::load_matrix_sync(bfv[1], Bs + kk * 80 + wn * 32 + 16, 80);
            if constexpr (ACOL) {
                wmma::fragment<wmma::matrix_a, 16, 16, 16, bf16, wmma::col_major> af[2];
                wmma::load_matrix_sync(af[0], As + kk * 144 + wm * 32,      144);
                wmma::load_matrix_sync(af[1], As + kk * 144 + wm * 32 + 16, 144);
                #pragma unroll
                for (int i = 0; i < 2; i++)
                    #pragma unroll
                    for (int j = 0; j < 2; j++)
                        wmma::mma_sync(acc[i][j], af[i], bfv[j], acc[i][j]);
            } else {
                wmma::fragment<wmma::matrix_a, 16, 16, 16, bf16, wmma::row_major> af[2];
                wmma::load_matrix_sync(af[0], As + (wm * 32)     * 48 + kk, 48);
                wmma::load_matrix_sync(af[1], As + (wm * 32 + 16) * 48 + kk, 48);
                #pragma unroll
                for (int i = 0; i < 2; i++)
                    #pragma unroll
                    for (int j = 0; j < 2; j++)
                        wmma::mma_sync(acc[i][j], af[i], bfv[j], acc[i][j]);
            }
        }
        __syncthreads();
    }

    #pragma unroll
    for (int i = 0; i < 2; i++)
        #pragma unroll
        for (int j = 0; j < 2; j++)
            wmma::store_matrix_sync(Csm + (wm * 32 + i * 16) * 72 + wn * 32 + j * 16,
                                    acc[i][j], 72, wmma::mem_row_major);
    __syncthreads();

    if (MODE == 0) {            // transposed store into g_cat channel-major
        // 64 columns (j) x 128 rows; each thread: one column, 32 rows.
        int b = m0 >> 12, p0 = m0 & 4095;
        int j = tid >> 2;                  // 0..63
        int part = tid & 3;                // 0..3 -> rows part*32 .. part*32+31
        bf16* dst = g_cat + ((size_t)b * 3072 + n0 + j) * 4096 + p0 + part * 32;
        #pragma unroll
        for (int k0 = 0; k0 < 32; k0 += 8) {
            uint4 pack; bf16* t = (bf16*)&pack;
            #pragma unroll
            for (int u = 0; u < 8; u++)
                t[u] = __float2bfloat16(Csm[(part * 32 + k0 + u) * 72 + j]);
            *(uint4*)(dst + k0) = pack;
        }
    } else if (MODE == 1) {     // row-major bf16 msq
        bf16* dst = g_msq + (size_t)z * 4096 * 768;
        int r = tid >> 1, hc = (tid & 1) * 32;
        #pragma unroll
        for (int c = 0; c < 32; c += 8) {
            uint4 pack; bf16* t = (bf16*)&pack;
            #pragma unroll
            for (int u = 0; u < 8; u++)
                t[u] = __float2bfloat16(Csm[r * 72 + hc + c + u]);
            *(uint4*)(dst + (size_t)(m0 + r) * 768 + n0 + hc + c) = pack;
        }
    } else {                    // fp32 + bias
        int r = tid >> 1, hc = (tid & 1) * 32;
        #pragma unroll
        for (int c = 0; c < 32; c += 4) {
            float4 v;
            v.x = Csm[r * 72 + hc + c + 0] + bias[n0 + hc + c + 0];
            v.y = Csm[r * 72 + hc + c + 1] + bias[n0 + hc + c + 1];
            v.z = Csm[r * 72 + hc + c + 2] + bias[n0 + hc + c + 2];
            v.w = Csm[r * 72 + hc + c + 3] + bias[n0 + hc + c + 3];
            *(float4*)(OUT + (size_t)(m0 + r) * 512 + n0 + hc + c) = v;
        }
    }
}

// ---------------- flash attention: 32 problems of [2048,32] ----------------
// grid: x = q-tile (16), y = problem (32). 256 threads.
#define OFF_Q  0
#define OFF_K  12288
#define OFF_V  24576
#define OFF_S  36864      // fp32 128x136
#define OFF_P  106496     // bf16 128x144
#define OFF_PV 143360     // fp32 128x40
#define OFF_O  163840     // fp32 128x32
#define OFF_M  180224
#define OFF_L  180736
#define OFF_C  181248
#define ATT_SMEM 181760

__global__ void k_attn() {
    extern __shared__ char sm[];
    bf16*  Qs   = (bf16*) (sm + OFF_Q);
    bf16*  Ks   = (bf16*) (sm + OFF_K);
    bf16*  Vs   = (bf16*) (sm + OFF_V);
    float* Ssm  = (float*)(sm + OFF_S);
    bf16*  Ps   = (bf16*) (sm + OFF_P);
    float* PVs  = (float*)(sm + OFF_PV);
    float* Osm  = (float*)(sm + OFF_O);
    float* mrow = (float*)(sm + OFF_M);
    float* lrow = (float*)(sm + OFF_L);
    float* crow = (float*)(sm + OFF_C);

    const int tid  = threadIdx.x;
    const int warp = tid >> 5;
    const int b = blockIdx.y >> 4;
    const int h = (blockIdx.y >> 1) & 7;
    const int c = blockIdx.y & 1;
    const int q0 = blockIdx.x * 128;

    const bf16* base = g_msq + ((size_t)b * 4096 + c * 2048) * 768;
    const bf16* qp = base + h * 32;
    const bf16* kp = base + 256 + h * 32;
    const bf16* vp = base + 512 + h * 32;

    #pragma unroll
    for (int it = 0; it < 2; it++) {
        int u = tid + it * 256;
        int r = u >> 2, dd = (u & 3) * 8;
        uint4 v = *(const uint4*)(qp + (size_t)(q0 + r) * 768 + dd);
        bf16* pv = (bf16*)&v;
        uint4 pack; bf16* t = (bf16*)&pack;
        #pragma unroll
        for (int i = 0; i < 8; i++)
            t[i] = __float2bfloat16(__bfloat162float(pv[i]) * ATT_SCALE);
        *(uint4*)(Qs + r * 48 + dd) = pack;
    }
    for (int e = tid; e < 4096; e += 256) Osm[e] = 0.f;
    if (tid < 128) { mrow[tid] = -1e30f; lrow[tid] = 0.f; }
    __syncthreads();

    const int wq = warp >> 1, wk = warp & 1;
    for (int kv0 = 0; kv0 < 2048; kv0 += 128) {
        #pragma unroll
        for (int it = 0; it < 2; it++) {
            int u = tid + it * 256;
            int r = u >> 2, dd = (u & 3) * 8;
            *(uint4*)(Ks + r * 48 + dd) = *(const uint4*)(kp + (size_t)(kv0 + r) * 768 + dd);
            *(uint4*)(Vs + r * 48 + dd) = *(const uint4*)(vp + (size_t)(kv0 + r) * 768 + dd);
        }
        __syncthreads();

        // S = (Q*scale) @ K^T   (warp tile 32x64)
        wmma::fragment<wmma::accumulator, 16, 16, 16, float> accS[2][4];
        #pragma unroll
        for (int i = 0; i < 2; i++)
            #pragma unroll
            for (int j = 0; j < 4; j++) wmma::fill_fragment(accS[i][j], 0.f);
        #pragma unroll
        for (int d0 = 0; d0 < 32; d0 += 16) {
            wmma::fragment<wmma::matrix_a, 16, 16, 16, bf16, wmma::row_major> af[2];
            wmma::load_matrix_sync(af[0], Qs + (wq * 32)     * 48 + d0, 48);
            wmma::load_matrix_sync(af[1], Qs + (wq * 32 + 16) * 48 + d0, 48);
            #pragma unroll
            for (int j = 0; j < 4; j++) {
                wmma::fragment<wmma::matrix_b, 16, 16, 16, bf16, wmma::col_major> bfr;
                wmma::load_matrix_sync(bfr, Ks + (wk * 64 + j * 16) * 48 + d0, 48);
                wmma::mma_sync(accS[0][j], af[0], bfr, accS[0][j]);
                wmma::mma_sync(accS[1][j], af[1], bfr, accS[1][j]);
            }
        }
        #pragma unroll
        for (int i = 0; i < 2; i++)
            #pragma unroll
            for (int j = 0; j < 4; j++)
                wmma::store_matrix_sync(Ssm + (wq * 32 + i * 16) * 136 + wk * 64 + j * 16,
                                        accS[i][j], 136, wmma::mem_row_major);
        __syncthreads();

        // online softmax (2 threads per row)
        {
            int r = tid >> 1, cb = (tid & 1) * 64;
            float mloc = -1e30f;
            #pragma unroll 8
            for (int cc = 0; cc < 64; cc++) mloc = fmaxf(mloc, Ssm[r * 136 + cb + cc]);
            mloc = fmaxf(mloc, __shfl_xor_sync(0xffffffffu, mloc, 1));
            float mold = mrow[r];
            float mnew = fmaxf(mold, mloc);
            float s = 0.f;
            #pragma unroll 8
            for (int cc = 0; cc < 64; cc++) {
                float pe = __expf(Ssm[r * 136 + cb + cc] - mnew);
                s += pe;
                Ps[r * 144 + cb + cc] = __float2bfloat16(pe);
            }
            s += __shfl_xor_sync(0xffffffffu, s, 1);
            if ((tid & 1) == 0) {
                float cr = __expf(mold - mnew);
                crow[r] = cr;
                lrow[r] = lrow[r] * cr + s;
                mrow[r] = mnew;
            }
        }
        __syncthreads();

        // PV = P @ V   (each warp: 16 rows x 32 cols)
        {
            wmma::fragment<wmma::accumulator, 16, 16, 16, float> accO[2];
            wmma::fill_fragment(accO[0], 0.f);
            wmma::fill_fragment(accO[1], 0.f);
            #pragma unroll
            for (int kk = 0; kk < 128; kk += 16) {
                wmma::fragment<wmma::matrix_a, 16, 16, 16, bf16, wmma::row_major> af;
                wmma::load_matrix_sync(af, Ps + (warp * 16) * 144 + kk, 144);
                #pragma unroll
                for (int j = 0; j < 2; j++) {
                    wmma::fragment<wmma::matrix_b, 16, 16, 16, bf16, wmma::row_major> bfr;
                    wmma::load_matrix_sync(bfr, Vs + kk * 48 + j * 16, 48);
                    wmma::mma_sync(accO[j], af, bfr, accO[j]);
                }
            }
            wmma::store_matrix_sync(PVs + warp * 16 * 40,      accO[0], 40, wmma::mem_row_major);
            wmma::store_matrix_sync(PVs + warp * 16 * 40 + 16, accO[1], 40, wmma::mem_row_major);
        }
        __syncthreads();
        for (int e = tid; e < 4096; e += 256) {
            int r = e >> 5, d = e & 31;
            Osm[e] = Osm[e] * crow[r] + PVs[r * 40 + d];
        }
        __syncthreads();
    }

    for (int e = tid; e < 4096; e += 256) {
        int r = e >> 5, d = e & 31;
        float v = Osm[e] / lrow[r];
        int token = c * 2048 + q0 + r;
        g_ao[((size_t)b * 4096 + token) * 256 + h * 32 + d] = __float2bfloat16(v);
    }
}

// ---------------- launch ---------------------------------------------------
extern "C" void kernel_launch(void* const* d_in, const int* in_sizes, int n_in,
                              void* d_out, int out_size) {
    const float* x         = (const float*)d_in[0];
    const float* w_reduce  = (const float*)d_in[1];
    const float* w_qkv     = (const float*)d_in[2];
    const float* dw0       = (const float*)d_in[3];
    const float* pw0       = (const float*)d_in[4];
    const float* dw1       = (const float*)d_in[5];
    const float* pw1       = (const float*)d_in[6];
    const float* dw2       = (const float*)d_in[7];
    const float* pw2       = (const float*)d_in[8];
    const float* w_reduce2 = (const float*)d_in[9];
    const float* w_proj    = (const float*)d_in[10];
    const float* b_proj    = (const float*)d_in[11];
    float* out = (float*)d_out;

    cudaFuncSetAttribute(k_attn, cudaFuncAttributeMaxDynamicSharedMemorySize, ATT_SMEM);

    // weight folds + converts (independent)
    k_convert<0><<<4096, 256>>>(x);                    // x -> bf16
    k_convert<1><<<576, 256>>>(w_reduce2);             // first 768 rows of W2f
    k_convert<2><<<128, 256>>>(w_proj);                // w_proj -> bf16
    k_fold_w1<<<64, 256>>>(w_reduce, w_qkv);
    k_fold_w2<<<dim3(24, 3), 256>>>(pw0, pw1, pw2, w_reduce2);

    // G1: qkv = xb @ W1  -> g_cat (channel-major, branch 0)
    k_gemm<0><<<dim3(12, 64, 1), 256, 36864>>>(nullptr, nullptr);

    // depthwise convs -> g_cat branches 1..3
    k_conv<<<dim3(768, 2), 256>>>(dw0, dw1, dw2);

    // G2: msq = cat^T @ W2f  (per batch)
    k_gemm<1><<<dim3(12, 32, 2), 256, 36864>>>(nullptr, nullptr);

    // chunked flash attention
    k_attn<<<dim3(16, 32), 256, ATT_SMEM>>>();

    // G3: out = ao @ wp + bias
    k_gemm<2><<<dim3(8, 64, 1), 256, 36864>>>(out, b_proj);
}